// round 12
// baseline (speedup 1.0000x reference)
#include <cuda_runtime.h>
#include <cstdint>

#define Bn 16
#define Cn 256
#define Ln 4096
#define Pn 100
#define Qn 20
#define TL 128                   // l-tile (4 l per thread)
#define NT2 (Bn * (Ln / TL))     // 512 tiles
#define NW 12                    // warps per block
#define KP 9                     // p per warp: p = 9w + k (100..107 zero-padded)
#define PPAD (NW * KP)           // 108
#define NTHR (NW * 32)           // 384
#define GRID 148
#define XRS 132                  // X row stride (words): 528B, 16B-aligned, 4-bank step
#define XARR (32 * XRS + 8)      // 4232 words per X_m array; +8 skews banks per m

__global__ void zero_cdf_kernel(float* out) {
    int i = blockIdx.x * 256 + threadIdx.x;
    if (i < Bn * Pn * Qn) out[i] = 0.0f;
}

__device__ __forceinline__ unsigned long long ffma2(unsigned long long a,
                                                    unsigned long long b,
                                                    unsigned long long c) {
    unsigned long long d;
    asm("fma.rn.f32x2 %0, %1, %2, %3;" : "=l"(d) : "l"(a), "l"(b), "l"(c));
    return d;
}
__device__ __forceinline__ void unpack2(unsigned long long v, float& x, float& y) {
    asm("mov.b64 {%0,%1}, %2;" : "=f"(x), "=f"(y) : "l"(v));
}

// item = (h, cc): lanes load column l0 + 32h + lane, rows (4cc..4cc+3) of current c-half.
__device__ __forceinline__ float4 load_item(const float* Xc, int lane, int item) {
    int cc = item & 31, h = item >> 5;
    const float* s = Xc + (size_t)(4 * cc) * Ln + 32 * h + lane;
    float4 v;
    v.x = __ldcs(s);
    v.y = __ldcs(s + Ln);
    v.z = __ldcs(s + 2 * Ln);
    v.w = __ldcs(s + 3 * Ln);
    return v;
}
// STS.128 into X_m arrays (m = l&3, row = l>>2). Bank-verified conflict-free.
__device__ __forceinline__ void stage_item(float* Xs, int lane, int item, float4 v) {
    int cc = item & 31, h = item >> 5;
    int m = lane & 3, row = 8 * h + (lane >> 2);
    *(float4*)(Xs + m * XARR + row * XRS + 4 * cc) = v;
}

__global__ __launch_bounds__(NTHR, 1)
void csf_persistent_kernel(const float* __restrict__ X,
                           const float* __restrict__ proj,
                           const float* __restrict__ minv,
                           const float* __restrict__ maxv,
                           float* __restrict__ out) {
    extern __shared__ float sm[];
    float* Xs  = sm;                       // 4 arrays of [32][XRS]
    float* pst = sm + 4 * XARR;            // [PPAD][Cn], rows >= Pn zero
    float* thr = pst + PPAD * Cn;          // [Pn*Qn]

    const int tid  = threadIdx.x;
    const int w    = tid >> 5;
    const int lane = tid & 31;

    // ---- One-time staging: projections (zero-pad) + thresholds ----
    {
        const int total4 = PPAD * Cn / 4;
        const int lim4   = Pn * Cn / 4;
        for (int i = tid; i < total4; i += NTHR) {
            float4 v = make_float4(0.f, 0.f, 0.f, 0.f);
            if (i < lim4) v = ((const float4*)proj)[i];
            ((float4*)pst)[i] = v;
        }
        for (int i = tid; i < Pn * Qn; i += NTHR) {
            int p = i / Qn, q = i % Qn;
            float f = (float)(q + 1) / (float)(Qn + 1);
            thr[i] = minv[p] + (maxv[p] - minv[p]) * f;
        }
    }

    const int pbase = KP * w;
    const float* psb = pst + pbase * Cn;

    int t = blockIdx.x;   // always < NT2 (148 <= 512)

    // Prologue: stage c-half A of first tile (128 items over 12 warps, ragged).
    {
        const float* Xc = X + (size_t)(t >> 5) * Cn * Ln + (size_t)(t & 31) * TL;
        #pragma unroll
        for (int j = 0; j < 11; j++) {
            int it = j * NW + w;
            if (it < 128) stage_item(Xs, lane, it, load_item(Xc, lane, it));
        }
    }
    __syncthreads();

    while (true) {
        const int b  = t >> 5;
        const int l0 = (t & 31) * TL;
        const float* Xbase = X + (size_t)b * Cn * Ln + l0;

        unsigned long long acc[KP][4];
        #pragma unroll
        for (int k = 0; k < KP; k++)
            #pragma unroll
            for (int m = 0; m < 4; m++) acc[k][m] = 0ull;

        // ---- Prefetch c-half B while computing on half A ----
        float4 pf[11];
        {
            const float* XcB = Xbase + (size_t)128 * Ln;
            #pragma unroll
            for (int j = 0; j < 11; j++) {
                int it = j * NW + w;
                if (it < 128) pf[j] = load_item(XcB, lane, it);
            }
        }

        // ---- Compute phase A: c in [0,128) ----
        #pragma unroll 2
        for (int c = 0; c < 128; c += 4) {
            ulonglong2 xv[4];
            #pragma unroll
            for (int m = 0; m < 4; m++)
                xv[m] = *(const ulonglong2*)(Xs + m * XARR + lane * XRS + c);
            #pragma unroll
            for (int k = 0; k < KP; k++) {
                ulonglong2 pv = *(const ulonglong2*)(psb + k * Cn + c);  // broadcast
                #pragma unroll
                for (int m = 0; m < 4; m++) {
                    acc[k][m] = ffma2(pv.x, xv[m].x, acc[k][m]);
                    acc[k][m] = ffma2(pv.y, xv[m].y, acc[k][m]);
                }
            }
        }

        __syncthreads();                 // all warps done reading half A
        #pragma unroll
        for (int j = 0; j < 11; j++) {
            int it = j * NW + w;
            if (it < 128) stage_item(Xs, lane, it, pf[j]);
        }
        __syncthreads();                 // half B staged

        // ---- Prefetch next tile's half A while computing on half B ----
        const int tn = t + GRID;
        const bool have = (tn < NT2);
        if (have) {
            const float* XcA = X + (size_t)(tn >> 5) * Cn * Ln + (size_t)(tn & 31) * TL;
            #pragma unroll
            for (int j = 0; j < 11; j++) {
                int it = j * NW + w;
                if (it < 128) pf[j] = load_item(XcA, lane, it);
            }
        }

        // ---- Compute phase B: c in [128,256) ----
        #pragma unroll 2
        for (int c = 0; c < 128; c += 4) {
            ulonglong2 xv[4];
            #pragma unroll
            for (int m = 0; m < 4; m++)
                xv[m] = *(const ulonglong2*)(Xs + m * XARR + lane * XRS + c);
            #pragma unroll
            for (int k = 0; k < KP; k++) {
                ulonglong2 pv = *(const ulonglong2*)(psb + k * Cn + 128 + c);
                #pragma unroll
                for (int m = 0; m < 4; m++) {
                    acc[k][m] = ffma2(pv.x, xv[m].x, acc[k][m]);
                    acc[k][m] = ffma2(pv.y, xv[m].y, acc[k][m]);
                }
            }
        }

        if (have) {
            __syncthreads();             // all warps done reading half B
            #pragma unroll
            for (int j = 0; j < 11; j++) {
                int it = j * NW + w;
                if (it < 128) stage_item(Xs, lane, it, pf[j]);
            }
            __syncthreads();             // next tile half A staged
        }

        // ---- Epilogue(t): set stores (STG.128) + cdf counts ----
        float* cdfb = out + b * (Pn * Qn);
        float* setb = out + Bn * Pn * Qn + (size_t)b * Pn * Qn * Ln;

        #pragma unroll
        for (int k = 0; k < KP; k++) {
            const int p = pbase + k;
            if (p >= Pn) break;          // uniform within warp (only warp 11)
            float a[4];
            #pragma unroll
            for (int m = 0; m < 4; m++) {
                float e, o;
                unpack2(acc[k][m], e, o);
                a[m] = e + o;            // l = l0 + 4*lane + m
            }

            float4* dst = (float4*)(setb + (size_t)p * Qn * Ln + l0) + lane;
            const float* th = thr + p * Qn;

            #pragma unroll
            for (int qq = 0; qq < Qn; qq += 4) {
                unsigned packed = 0;
                #pragma unroll
                for (int j = 0; j < 4; j++) {
                    float tt = th[qq + j];
                    bool c0 = (a[0] < tt), c1 = (a[1] < tt);
                    bool c2 = (a[2] < tt), c3 = (a[3] < tt);
                    float4 s;
                    s.x = c0 ? 1.0f : 0.0f;
                    s.y = c1 ? 1.0f : 0.0f;
                    s.z = c2 ? 1.0f : 0.0f;
                    s.w = c3 ? 1.0f : 0.0f;
                    dst[(size_t)(qq + j) * (Ln / 4)] = s;
                    unsigned cnt = (unsigned)c0 + (unsigned)c1 + (unsigned)c2 + (unsigned)c3;
                    packed += cnt << (8 * j);          // per-byte sum <= 128
                }
                unsigned r = __reduce_add_sync(0xffffffffu, packed);
                if (lane < 4) {
                    float v = (float)((r >> (8 * lane)) & 255u) * (1.0f / 4096.0f);
                    atomicAdd(cdfb + p * Qn + qq + lane, v);   // exact dyadic
                }
            }
        }

        if (!have) break;
        t = tn;
    }
}

extern "C" void kernel_launch(void* const* d_in, const int* in_sizes, int n_in,
                              void* d_out, int out_size) {
    const float* X    = (const float*)d_in[0];
    const float* proj = (const float*)d_in[1];
    const float* minv = (const float*)d_in[2];
    const float* maxv = (const float*)d_in[3];
    float* out = (float*)d_out;

    zero_cdf_kernel<<<(Bn * Pn * Qn + 255) / 256, 256>>>(out);

    const int smem = (4 * XARR + PPAD * Cn + Pn * Qn) * (int)sizeof(float);
    cudaFuncSetAttribute(csf_persistent_kernel,
                         cudaFuncAttributeMaxDynamicSharedMemorySize, smem);
    csf_persistent_kernel<<<GRID, NTHR, smem>>>(X, proj, minv, maxv, out);
}

// round 13
// speedup vs baseline: 1.1968x; 1.1968x over previous
#include <cuda_runtime.h>
#include <cstdint>

#define Bn 16
#define Cn 256
#define Ln 4096
#define Pn 100
#define Qn 20
#define TL 64
#define SROW 260                 // word stride of Xe/Xo rows (1040B, 16B-aligned)
#define NW 16                    // warps per block
#define KP 7                     // p per warp: p = 7w + k (100..111 zero-padded)
#define PPAD (NW * KP)           // 112
#define NTILES (Bn * (Ln / TL))  // 1024
#define GRID 148
#define NTHR (NW * 32)           // 512
#define XO_OFF (32 * SROW + 16)  // Xo base: +16 words -> odd-lane STS banks disjoint

__global__ void zero_cdf_kernel(float* out) {
    int i = blockIdx.x * 256 + threadIdx.x;
    if (i < Bn * Pn * Qn) out[i] = 0.0f;
}

__device__ __forceinline__ unsigned long long ffma2(unsigned long long a,
                                                    unsigned long long b,
                                                    unsigned long long c) {
    unsigned long long d;
    asm("fma.rn.f32x2 %0, %1, %2, %3;" : "=l"(d) : "l"(a), "l"(b), "l"(c));
    return d;
}
__device__ __forceinline__ void unpack2(unsigned long long v, float& x, float& y) {
    asm("mov.b64 {%0,%1}, %2;" : "=f"(x), "=f"(y) : "l"(v));
}

// item = (cc, h): warp loads c = 4cc..4cc+3 for l = 32h + lane.  item in [0,128)
__device__ __forceinline__ float4 load_item(const float* Xb, int lane, int item) {
    int cc = item >> 1, h = item & 1;
    const float* s = Xb + (size_t)(4 * cc) * Ln + 32 * h + lane;
    float4 v;
    v.x = __ldcs(s);
    v.y = __ldcs(s + Ln);
    v.z = __ldcs(s + 2 * Ln);
    v.w = __ldcs(s + 3 * Ln);
    return v;
}
// STS.128, conflict-free per 8-lane phase (evens->Xe banks {0..15}+c0, odds->Xo {16..31}+c0)
__device__ __forceinline__ void stage_item(float* Xe, int lane, int item, float4 v) {
    int cc = item >> 1, h = item & 1;
    int r = 16 * h + (lane >> 1);
    float* base = Xe + ((lane & 1) ? XO_OFF : 0) + r * SROW + 4 * cc;
    *(float4*)base = v;
}

__global__ __launch_bounds__(NTHR, 1)
void csf_persistent_kernel(const float* __restrict__ X,
                           const float* __restrict__ proj,
                           const float* __restrict__ minv,
                           const float* __restrict__ maxv,
                           float* __restrict__ out) {
    extern __shared__ float sm[];
    float* Xe  = sm;                         // rows: l=2r; Xo at +XO_OFF: l=2r+1
    float* pst = sm + XO_OFF + 32 * SROW;    // [PPAD][Cn], rows >= Pn zero
    float* thr = pst + PPAD * Cn;            // [Pn*Qn]

    const int tid  = threadIdx.x;
    const int w    = tid >> 5;
    const int lane = tid & 31;

    // ---- One-time staging: projections (zero-pad) + thresholds ----
    {
        const int total4 = PPAD * Cn / 4;    // 7168
        const int lim4   = Pn * Cn / 4;      // 6400
        for (int i = tid; i < total4; i += NTHR) {
            float4 v = make_float4(0.f, 0.f, 0.f, 0.f);
            if (i < lim4) v = ((const float4*)proj)[i];
            ((float4*)pst)[i] = v;
        }
        for (int i = tid; i < Pn * Qn; i += NTHR) {
            int p = i / Qn, q = i % Qn;
            float f = (float)(q + 1) / (float)(Qn + 1);
            thr[i] = minv[p] + (maxv[p] - minv[p]) * f;
        }
    }

    const int pbase = KP * w;
    const float* psb = pst + pbase * Cn;
    const float* xa = Xe + lane * SROW;            // l = l0 + 2*lane
    const float* xb = Xe + XO_OFF + lane * SROW;   // l = l0 + 2*lane + 1

    int t = blockIdx.x;
    if (t >= NTILES) return;

    // Prologue: stage first tile (128 items = 8 rounds x 16 warps, exact).
    {
        const float* Xb = X + (size_t)(t >> 6) * Cn * Ln + (t & 63) * TL;
        #pragma unroll
        for (int j = 0; j < 8; j++)
            stage_item(Xe, lane, j * NW + w, load_item(Xb, lane, j * NW + w));
    }
    __syncthreads();

    while (true) {
        const int b  = t >> 6;
        const int l0 = (t & 63) * TL;

        // ---- Compute: warp w owns p = 7w..7w+6 (padded rows are zeros) ----
        // 8-c window: burst 4 x-LDS.128 up front, then per-k 2 proj-LDS + 8 FFMA2.
        unsigned long long acc0[KP], acc1[KP];
        #pragma unroll
        for (int k = 0; k < KP; k++) { acc0[k] = 0ull; acc1[k] = 0ull; }

        #pragma unroll 2
        for (int c = 0; c < Cn; c += 8) {
            ulonglong2 x0a = *(const ulonglong2*)(xa + c);
            ulonglong2 x0b = *(const ulonglong2*)(xa + c + 4);
            ulonglong2 x1a = *(const ulonglong2*)(xb + c);
            ulonglong2 x1b = *(const ulonglong2*)(xb + c + 4);
            #pragma unroll
            for (int k = 0; k < KP; k++) {
                ulonglong2 pva = *(const ulonglong2*)(psb + k * Cn + c);      // broadcast
                ulonglong2 pvb = *(const ulonglong2*)(psb + k * Cn + c + 4);  // broadcast
                acc0[k] = ffma2(pva.x, x0a.x, acc0[k]);
                acc0[k] = ffma2(pva.y, x0a.y, acc0[k]);
                acc0[k] = ffma2(pvb.x, x0b.x, acc0[k]);
                acc0[k] = ffma2(pvb.y, x0b.y, acc0[k]);
                acc1[k] = ffma2(pva.x, x1a.x, acc1[k]);
                acc1[k] = ffma2(pva.y, x1a.y, acc1[k]);
                acc1[k] = ffma2(pvb.x, x1b.x, acc1[k]);
                acc1[k] = ffma2(pvb.y, x1b.y, acc1[k]);
            }
        }

        // ---- Prefetch ENTIRE next tile into registers (hidden by epilogue) ----
        const int tn = t + GRID;
        const bool have = (tn < NTILES);
        float4 pf[8];
        if (have) {
            const float* Xb2 = X + (size_t)(tn >> 6) * Cn * Ln + (tn & 63) * TL;
            #pragma unroll
            for (int j = 0; j < 8; j++)
                pf[j] = load_item(Xb2, lane, j * NW + w);
        }

        // ---- Epilogue: set stores + cdf counts ----
        float* cdfb = out + b * (Pn * Qn);
        float* setb = out + Bn * Pn * Qn + (size_t)b * Pn * Qn * Ln;

        #pragma unroll
        for (int k = 0; k < KP; k++) {
            const int p = pbase + k;
            if (p >= Pn) break;   // uniform within warp
            float e0, o0, e1, o1;
            unpack2(acc0[k], e0, o0);
            unpack2(acc1[k], e1, o1);
            float a0 = e0 + o0;   // l = l0 + 2*lane
            float a1 = e1 + o1;   // l = l0 + 2*lane + 1

            float2* dst = (float2*)(setb + (size_t)p * Qn * Ln + l0) + lane;
            const float* th = thr + p * Qn;

            #pragma unroll
            for (int qq = 0; qq < Qn; qq += 4) {
                unsigned packed = 0;
                #pragma unroll
                for (int j = 0; j < 4; j++) {
                    float tt = th[qq + j];
                    bool c0 = (a0 < tt);
                    bool c1 = (a1 < tt);
                    float f0 = c0 ? 1.0f : 0.0f;
                    float f1 = c1 ? 1.0f : 0.0f;
                    dst[(size_t)(qq + j) * (Ln / 2)] = make_float2(f0, f1);
                    unsigned cnt = (c0 ? 1u : 0u) + (c1 ? 1u : 0u);
                    packed += cnt << (8 * j);          // per-byte sum <= 64
                }
                unsigned r = __reduce_add_sync(0xffffffffu, packed);
                if (lane < 4) {
                    float v = (float)((r >> (8 * lane)) & 255u) * (1.0f / 4096.0f);
                    atomicAdd(cdfb + p * Qn + qq + lane, v);   // exact dyadic
                }
            }
        }

        if (!have) break;

        __syncthreads();   // all warps done reading Xe/Xo
        #pragma unroll
        for (int j = 0; j < 8; j++)
            stage_item(Xe, lane, j * NW + w, pf[j]);
        __syncthreads();   // tile ready

        t = tn;
    }
}

extern "C" void kernel_launch(void* const* d_in, const int* in_sizes, int n_in,
                              void* d_out, int out_size) {
    const float* X    = (const float*)d_in[0];
    const float* proj = (const float*)d_in[1];
    const float* minv = (const float*)d_in[2];
    const float* maxv = (const float*)d_in[3];
    float* out = (float*)d_out;

    zero_cdf_kernel<<<(Bn * Pn * Qn + 255) / 256, 256>>>(out);

    const int smem = (XO_OFF + 32 * SROW + PPAD * Cn + Pn * Qn) * (int)sizeof(float);
    cudaFuncSetAttribute(csf_persistent_kernel,
                         cudaFuncAttributeMaxDynamicSharedMemorySize, smem);
    csf_persistent_kernel<<<GRID, NTHR, smem>>>(X, proj, minv, maxv, out);
}

// round 14
// speedup vs baseline: 1.2255x; 1.0240x over previous
#include <cuda_runtime.h>
#include <cstdint>

#define Bn 16
#define Cn 256
#define Ln 4096
#define Pn 100
#define Qn 20
#define TL 64
#define SROW 260                 // word stride of Xe/Xo rows (1040B, 16B-aligned)
#define NW 16                    // warps per block
#define KP 7                     // p per warp: p = 7w + k (100..111 zero-padded)
#define PPAD (NW * KP)           // 112
#define NTILES (Bn * (Ln / TL))  // 1024
#define GRID 148
#define NTHR (NW * 32)           // 512
#define XO_OFF (32 * SROW + 16)  // Xo base: +16 words -> odd-lane STS banks disjoint

__global__ void zero_cdf_kernel(float* out) {
    int i = blockIdx.x * 256 + threadIdx.x;
    if (i < Bn * Pn * Qn) out[i] = 0.0f;
}

__device__ __forceinline__ unsigned long long ffma2(unsigned long long a,
                                                    unsigned long long b,
                                                    unsigned long long c) {
    unsigned long long d;
    asm("fma.rn.f32x2 %0, %1, %2, %3;" : "=l"(d) : "l"(a), "l"(b), "l"(c));
    return d;
}
__device__ __forceinline__ void unpack2(unsigned long long v, float& x, float& y) {
    asm("mov.b64 {%0,%1}, %2;" : "=f"(x), "=f"(y) : "l"(v));
}
// Streaming (evict-first) 8-byte store: keeps the 524MB one-touch set stream
// from thrashing L2 / paying write-allocate.
__device__ __forceinline__ void stg_cs_f2(float2* p, float x, float y) {
    asm volatile("st.global.cs.v2.f32 [%0], {%1,%2};" :: "l"(p), "f"(x), "f"(y) : "memory");
}

// item = (cc, h): warp loads c = 4cc..4cc+3 for l = 32h + lane.  item in [0,128)
__device__ __forceinline__ float4 load_item(const float* Xb, int lane, int item) {
    int cc = item >> 1, h = item & 1;
    const float* s = Xb + (size_t)(4 * cc) * Ln + 32 * h + lane;
    float4 v;
    v.x = __ldcs(s);
    v.y = __ldcs(s + Ln);
    v.z = __ldcs(s + 2 * Ln);
    v.w = __ldcs(s + 3 * Ln);
    return v;
}
// STS.128, conflict-free per 8-lane phase (evens->Xe banks {0..15}+c0, odds->Xo {16..31}+c0)
__device__ __forceinline__ void stage_item(float* Xe, int lane, int item, float4 v) {
    int cc = item >> 1, h = item & 1;
    int r = 16 * h + (lane >> 1);
    float* base = Xe + ((lane & 1) ? XO_OFF : 0) + r * SROW + 4 * cc;
    *(float4*)base = v;
}

__global__ __launch_bounds__(NTHR, 1)
void csf_persistent_kernel(const float* __restrict__ X,
                           const float* __restrict__ proj,
                           const float* __restrict__ minv,
                           const float* __restrict__ maxv,
                           float* __restrict__ out) {
    extern __shared__ float sm[];
    float* Xe  = sm;                         // rows: l=2r; Xo at +XO_OFF: l=2r+1
    float* pst = sm + XO_OFF + 32 * SROW;    // [PPAD][Cn], rows >= Pn zero
    float* thr = pst + PPAD * Cn;            // [Pn*Qn]

    const int tid  = threadIdx.x;
    const int w    = tid >> 5;
    const int lane = tid & 31;

    // ---- One-time staging: projections (zero-pad) + thresholds ----
    {
        const int total4 = PPAD * Cn / 4;    // 7168
        const int lim4   = Pn * Cn / 4;      // 6400
        for (int i = tid; i < total4; i += NTHR) {
            float4 v = make_float4(0.f, 0.f, 0.f, 0.f);
            if (i < lim4) v = ((const float4*)proj)[i];
            ((float4*)pst)[i] = v;
        }
        for (int i = tid; i < Pn * Qn; i += NTHR) {
            int p = i / Qn, q = i % Qn;
            float f = (float)(q + 1) / (float)(Qn + 1);
            thr[i] = minv[p] + (maxv[p] - minv[p]) * f;
        }
    }

    const int pbase = KP * w;
    const float* psb = pst + pbase * Cn;
    const float* xa = Xe + lane * SROW;            // l = l0 + 2*lane
    const float* xb = Xe + XO_OFF + lane * SROW;   // l = l0 + 2*lane + 1

    int t = blockIdx.x;
    if (t >= NTILES) return;

    // Prologue: stage first tile (128 items = 8 rounds x 16 warps, exact).
    {
        const float* Xb = X + (size_t)(t >> 6) * Cn * Ln + (t & 63) * TL;
        #pragma unroll
        for (int j = 0; j < 8; j++)
            stage_item(Xe, lane, j * NW + w, load_item(Xb, lane, j * NW + w));
    }
    __syncthreads();

    while (true) {
        const int b  = t >> 6;
        const int l0 = (t & 63) * TL;

        // ---- Compute: warp w owns p = 7w..7w+6 (padded rows are zeros) ----
        unsigned long long acc0[KP], acc1[KP];
        #pragma unroll
        for (int k = 0; k < KP; k++) { acc0[k] = 0ull; acc1[k] = 0ull; }

        #pragma unroll 2
        for (int c = 0; c < Cn; c += 8) {
            ulonglong2 x0a = *(const ulonglong2*)(xa + c);
            ulonglong2 x0b = *(const ulonglong2*)(xa + c + 4);
            ulonglong2 x1a = *(const ulonglong2*)(xb + c);
            ulonglong2 x1b = *(const ulonglong2*)(xb + c + 4);
            #pragma unroll
            for (int k = 0; k < KP; k++) {
                ulonglong2 pva = *(const ulonglong2*)(psb + k * Cn + c);      // broadcast
                ulonglong2 pvb = *(const ulonglong2*)(psb + k * Cn + c + 4);  // broadcast
                acc0[k] = ffma2(pva.x, x0a.x, acc0[k]);
                acc0[k] = ffma2(pva.y, x0a.y, acc0[k]);
                acc0[k] = ffma2(pvb.x, x0b.x, acc0[k]);
                acc0[k] = ffma2(pvb.y, x0b.y, acc0[k]);
                acc1[k] = ffma2(pva.x, x1a.x, acc1[k]);
                acc1[k] = ffma2(pva.y, x1a.y, acc1[k]);
                acc1[k] = ffma2(pvb.x, x1b.x, acc1[k]);
                acc1[k] = ffma2(pvb.y, x1b.y, acc1[k]);
            }
        }

        // ---- Prefetch ENTIRE next tile into registers (hidden by epilogue) ----
        const int tn = t + GRID;
        const bool have = (tn < NTILES);
        float4 pf[8];
        if (have) {
            const float* Xb2 = X + (size_t)(tn >> 6) * Cn * Ln + (tn & 63) * TL;
            #pragma unroll
            for (int j = 0; j < 8; j++)
                pf[j] = load_item(Xb2, lane, j * NW + w);
        }

        // ---- Epilogue: streaming set stores + cdf counts ----
        float* cdfb = out + b * (Pn * Qn);
        float* setb = out + Bn * Pn * Qn + (size_t)b * Pn * Qn * Ln;

        #pragma unroll
        for (int k = 0; k < KP; k++) {
            const int p = pbase + k;
            if (p >= Pn) break;   // uniform within warp
            float e0, o0, e1, o1;
            unpack2(acc0[k], e0, o0);
            unpack2(acc1[k], e1, o1);
            float a0 = e0 + o0;   // l = l0 + 2*lane
            float a1 = e1 + o1;   // l = l0 + 2*lane + 1

            float2* dst = (float2*)(setb + (size_t)p * Qn * Ln + l0) + lane;
            const float* th = thr + p * Qn;

            #pragma unroll
            for (int qq = 0; qq < Qn; qq += 4) {
                unsigned packed = 0;
                #pragma unroll
                for (int j = 0; j < 4; j++) {
                    float tt = th[qq + j];
                    bool c0 = (a0 < tt);
                    bool c1 = (a1 < tt);
                    float f0 = c0 ? 1.0f : 0.0f;
                    float f1 = c1 ? 1.0f : 0.0f;
                    stg_cs_f2(dst + (size_t)(qq + j) * (Ln / 2), f0, f1);
                    unsigned cnt = (c0 ? 1u : 0u) + (c1 ? 1u : 0u);
                    packed += cnt << (8 * j);          // per-byte sum <= 64
                }
                unsigned r = __reduce_add_sync(0xffffffffu, packed);
                if (lane < 4) {
                    float v = (float)((r >> (8 * lane)) & 255u) * (1.0f / 4096.0f);
                    atomicAdd(cdfb + p * Qn + qq + lane, v);   // exact dyadic
                }
            }
        }

        if (!have) break;

        __syncthreads();   // all warps done reading Xe/Xo
        #pragma unroll
        for (int j = 0; j < 8; j++)
            stage_item(Xe, lane, j * NW + w, pf[j]);
        __syncthreads();   // tile ready

        t = tn;
    }
}

extern "C" void kernel_launch(void* const* d_in, const int* in_sizes, int n_in,
                              void* d_out, int out_size) {
    const float* X    = (const float*)d_in[0];
    const float* proj = (const float*)d_in[1];
    const float* minv = (const float*)d_in[2];
    const float* maxv = (const float*)d_in[3];
    float* out = (float*)d_out;

    zero_cdf_kernel<<<(Bn * Pn * Qn + 255) / 256, 256>>>(out);

    const int smem = (XO_OFF + 32 * SROW + PPAD * Cn + Pn * Qn) * (int)sizeof(float);
    cudaFuncSetAttribute(csf_persistent_kernel,
                         cudaFuncAttributeMaxDynamicSharedMemorySize, smem);
    csf_persistent_kernel<<<GRID, NTHR, smem>>>(X, proj, minv, maxv, out);
}